// round 10
// baseline (speedup 1.0000x reference)
#include <cuda_runtime.h>
#include <cuda_bf16.h>
#include <stdint.h>

#define B_ 16
#define Q_ 100
#define G_ 16384
#define T_ 50
#define L_ 21
#define NCH 18
#define KB 64          // k elements per stage (full 128B bf16 row, single buffer)
#define MP 112         // padded M per GEMM (7 warps x 16)
#define NP 56          // padded N
#define TP 56          // g_D row stride
#define NT 224         // threads (7 warps; each warp: x-tile AND sigma-tile)
#define DEPTH 2        // cp.async pipeline depth
#define XSTG (Q_*KB*4) // 25600 B per f32 x stage
#define MSTG (T_*KB*4) // 12800 B per f32 m stage
#define DYNB (DEPTH*(XSTG+MSTG))   // 76800 B dynamic smem

// ---------------- device scratch (module statics, allocation-free) ----------------
__device__ float g_D1[B_*Q_*TP];   // dot(x, m)       (atomic-reduced)
__device__ float g_D2[B_*Q_*TP];   // dot(sig(x), m)  (atomic-reduced)
__device__ float g_Sneg[B_*Q_];
__device__ float g_Ssig[B_*Q_];
__device__ float g_Sm[B_*T_];

// ---------------- helpers ----------------
__device__ __forceinline__ uint32_t smem_u32(const void* p) {
    uint32_t a;
    asm("{ .reg .u64 t; cvta.to.shared.u64 t, %1; cvt.u32.u64 %0, t; }"
        : "=r"(a) : "l"(p));
    return a;
}
__device__ __forceinline__ uint32_t bf2(float lo, float hi) {
    uint32_t r;
    asm("cvt.rn.bf16x2.f32 %0, %1, %2;" : "=r"(r) : "f"(hi), "f"(lo));
    return r;
}
__device__ __forceinline__ float fast_tanh(float x) {
    float r;
    asm("tanh.approx.f32 %0, %1;" : "=f"(r) : "f"(x));
    return r;
}
__device__ __forceinline__ float fast_lg2(float x) {
    float r;
    asm("lg2.approx.f32 %0, %1;" : "=f"(r) : "f"(x));
    return r;
}
__device__ __forceinline__ void cp_async16(uint32_t saddr, const void* gptr) {
    asm volatile("cp.async.cg.shared.global [%0], [%1], 16;"
                 :: "r"(saddr), "l"(gptr) : "memory");
}
#define CP_COMMIT() asm volatile("cp.async.commit_group;" ::: "memory")
#define CP_WAIT1()  asm volatile("cp.async.wait_group 1;"  ::: "memory")
#define LDSM4(r0,r1,r2,r3,addr) \
    asm volatile("ldmatrix.sync.aligned.m8n8.x4.shared.b16 {%0,%1,%2,%3}, [%4];" \
        : "=r"(r0),"=r"(r1),"=r"(r2),"=r"(r3) : "r"(addr))
#define LDSM2(r0,r1,addr) \
    asm volatile("ldmatrix.sync.aligned.m8n8.x2.shared.b16 {%0,%1}, [%2];" \
        : "=r"(r0),"=r"(r1) : "r"(addr))
#define MMA16816(d,a,b0,b1) \
    asm volatile("mma.sync.aligned.m16n8k16.row.col.f32.bf16.bf16.f32 " \
        "{%0,%1,%2,%3},{%4,%5,%6,%7},{%8,%9},{%0,%1,%2,%3};" \
        : "+f"((d)[0]),"+f"((d)[1]),"+f"((d)[2]),"+f"((d)[3]) \
        : "r"((a)[0]),"r"((a)[1]),"r"((a)[2]),"r"((a)[3]),"r"(b0),"r"(b1))

// slot -> gmem byte offset within a batch-row-major f32 matrix (G*4 = 1<<16)
#define XGOFF(sl) ((uint32_t)(((sl) >> 4) << 16) | (uint32_t)(((sl) & 15) << 4))
// slot -> swizzled bf16 STS byte offset (row*128 + ((c4*8) ^ ((row&7)<<4)))
#define SWOFF(sl) ((uint32_t)((((sl) >> 4) * 128)) \
                 + (uint32_t)(((((sl) & 15) * 8)) ^ (((((sl) >> 4)) & 7) << 4)))

// ---------------- kernel 0: zero accumulators (vectorized) ----------------
__global__ void zero_kernel() {
    int i = blockIdx.x * blockDim.x + threadIdx.x;
    if (i < B_*Q_*TP/4) {
        reinterpret_cast<uint4*>(g_D1)[i] = make_uint4(0,0,0,0);
        reinterpret_cast<uint4*>(g_D2)[i] = make_uint4(0,0,0,0);
    }
    if (i < B_*Q_) { g_Sneg[i] = 0.f; g_Ssig[i] = 0.f; }
    if (i < B_*T_) { g_Sm[i] = 0.f; }
}

// ---------------- kernel 1: cp.async-staged convert + dual HMMA GEMM ----------------
// grid = (NCH, B_), block = 224, 2 CTAs/SM. Stage = KB=64 k-elements.
__global__ void __launch_bounds__(NT, 2)
pm_mma_kernel(const float* __restrict__ xg, const float* __restrict__ mg)
{
    __shared__ __align__(1024) __nv_bfloat16 sA[MP*64];   // x     14336 B
    __shared__ __align__(1024) __nv_bfloat16 sS[MP*64];   // sigma 14336 B
    __shared__ __align__(1024) __nv_bfloat16 sB[NP*64];   // m      7168 B
    extern __shared__ __align__(16) char dynsm[];
    char* xstage = dynsm;                 // DEPTH x 25600 B
    char* mstage = dynsm + DEPTH*XSTG;    // DEPTH x 12800 B

    const int b   = blockIdx.y;
    const int c   = blockIdx.x;
    const int tid = threadIdx.x;
    const int wid = tid >> 5;
    const int lid = tid & 31;

    // K split: 256 KB-units over 18 chunks -> 4x15 + 14x14
    const int nu = 14 + (c < 4 ? 1 : 0);
    const int u0 = c * 14 + (c < 4 ? c : 4);

    for (int i = tid; i < MP*64/8; i += NT) {
        reinterpret_cast<uint4*>(sA)[i] = make_uint4(0,0,0,0);
        reinterpret_cast<uint4*>(sS)[i] = make_uint4(0,0,0,0);
    }
    for (int i = tid; i < NP*64/8; i += NT)
        reinterpret_cast<uint4*>(sB)[i] = make_uint4(0,0,0,0);
    __syncthreads();

    const uint32_t sA32  = smem_u32(sA);
    const uint32_t sS32  = smem_u32(sS);
    const uint32_t sB32  = smem_u32(sB);
    const uint32_t xst32 = smem_u32(xstage);
    const uint32_t mst32 = smem_u32(mstage);

    // ---- ldmatrix address precompute (proven round-3 KB=64 formulas) ----
    const int mbase = wid * 16;
    const int arow  = mbase + (lid & 15);
    const uint32_t axor = (uint32_t)((arow & 7) << 4);
    const uint32_t akb0 = (uint32_t)((lid >> 4) << 4);
    const uint32_t arow128 = (uint32_t)(arow * 128);
    const int bg = lid >> 3, br = lid & 7;
    const uint32_t bxor = (uint32_t)(br << 4);
    const uint32_t bkb0 = (uint32_t)((bg & 1) << 4);
    const uint32_t brow_base = (uint32_t)(((bg >> 1) * 8 + br) * 128);
    const uint32_t brow6     = (uint32_t)((48 + br) * 128);

    // ---- gmem byte bases (per batch, advanced per stage) ----
    const char* xbase = reinterpret_cast<const char*>(xg)
                      + ((size_t)b * Q_ * G_ + (size_t)u0 * KB) * 4;
    const char* mbase_g = reinterpret_cast<const char*>(mg)
                      + ((size_t)b * T_ * G_ + (size_t)u0 * KB) * 4;

    float c1[7][4], c2[7][4];
    #pragma unroll
    for (int j = 0; j < 7; j++)
        #pragma unroll
        for (int u = 0; u < 4; u++) { c1[j][u] = 0.f; c2[j][u] = 0.f; }
    float aSP[8], aSG[8], aM[4];
    #pragma unroll
    for (int j = 0; j < 8; j++) { aSP[j] = 0.f; aSG[j] = 0.f; }
    #pragma unroll
    for (int j = 0; j < 4; j++) aM[j] = 0.f;

    // ---- prologue: issue cp.async for stages 0 and 1 ----
    #pragma unroll
    for (int pre = 0; pre < 2; pre++) {
        if (pre < nu) {
            const uint32_t xb = xst32 + pre * XSTG;
            const uint32_t mb2 = mst32 + pre * MSTG;
            const uint32_t kofs = (uint32_t)(pre * KB * 4);
            #pragma unroll
            for (int j = 0; j < 8; j++) {
                int sl = tid + NT * j;
                if (j == 7 && tid >= 32) continue;       // 1600 x-slots
                cp_async16(xb + (uint32_t)(sl * 16), xbase + XGOFF(sl) + kofs);
            }
            #pragma unroll
            for (int j = 0; j < 4; j++) {
                int sl = tid + NT * j;
                if (j == 3 && tid >= 128) continue;      // 800 m-slots
                cp_async16(mb2 + (uint32_t)(sl * 16), mbase_g + XGOFF(sl) + kofs);
            }
        }
        CP_COMMIT();
    }

    for (int s = 0; s < nu; s++) {
        const int buf = s & 1;

        CP_WAIT1();          // stage s landed (at most 1 group pending)
        __syncthreads();     // also: all warps done with MMA(s-1) ldmatrix

        // ---- convert f32 stage -> bf16 tiles (single buffer) ----
        const float4* xsrc = reinterpret_cast<const float4*>(xstage + buf * XSTG);
        const float4* msrc = reinterpret_cast<const float4*>(mstage + buf * MSTG);
        #pragma unroll
        for (int j = 0; j < 8; j++) {
            int sl = tid + NT * j;
            if (j == 7 && tid >= 32) continue;
            float4 v = xsrc[sl];
            float f[4] = { v.x, v.y, v.z, v.w };
            float sg[4];
            #pragma unroll
            for (int u = 0; u < 4; u++) {
                float x    = f[u];
                float t    = fast_tanh(0.5f * x);
                float sig  = fmaf(0.5f, t, 0.5f);
                float siga = fmaf(0.5f, fabsf(t), 0.5f);
                sg[u] = sig;
                aSG[j] += sig;
                aSP[j] += fmaxf(x, 0.f) - 0.69314718056f * fast_lg2(siga);
            }
            uint32_t off = SWOFF(sl);
            *reinterpret_cast<uint2*>(reinterpret_cast<char*>(sA) + off) =
                make_uint2(bf2(f[0], f[1]), bf2(f[2], f[3]));
            *reinterpret_cast<uint2*>(reinterpret_cast<char*>(sS) + off) =
                make_uint2(bf2(sg[0], sg[1]), bf2(sg[2], sg[3]));
        }
        #pragma unroll
        for (int j = 0; j < 4; j++) {
            int sl = tid + NT * j;
            if (j == 3 && tid >= 128) continue;
            float4 v = msrc[sl];
            aM[j] += v.x + v.y + v.z + v.w;
            *reinterpret_cast<uint2*>(reinterpret_cast<char*>(sB) + SWOFF(sl)) =
                make_uint2(bf2(v.x, v.y), bf2(v.z, v.w));
        }

        __syncthreads();     // bf16 tiles published; f32 buf fully consumed

        // ---- refill this f32 buffer with stage s+2 ----
        if (s + 2 < nu) {
            const uint32_t xb = xst32 + buf * XSTG;
            const uint32_t mb2 = mst32 + buf * MSTG;
            const uint32_t kofs = (uint32_t)((s + 2) * KB * 4);
            #pragma unroll
            for (int j = 0; j < 8; j++) {
                int sl = tid + NT * j;
                if (j == 7 && tid >= 32) continue;
                cp_async16(xb + (uint32_t)(sl * 16), xbase + XGOFF(sl) + kofs);
            }
            #pragma unroll
            for (int j = 0; j < 4; j++) {
                int sl = tid + NT * j;
                if (j == 3 && tid >= 128) continue;
                cp_async16(mb2 + (uint32_t)(sl * 16), mbase_g + XGOFF(sl) + kofs);
            }
        }
        CP_COMMIT();

        // ---- MMA: 4 k-steps x 7 n-tiles x 2 GEMMs (B frag reused) ----
        #pragma unroll
        for (int ks = 0; ks < 4; ks++) {
            const uint32_t aad = arow128 + (((uint32_t)(ks * 32) + akb0) ^ axor);
            uint32_t ax[4], as2[4];
            LDSM4(ax[0],  ax[1],  ax[2],  ax[3],  sA32 + aad);
            LDSM4(as2[0], as2[1], as2[2], as2[3], sS32 + aad);

            const uint32_t binner = (((uint32_t)(ks * 32) + bkb0) ^ bxor);
            #pragma unroll
            for (int p3 = 0; p3 < 3; p3++) {
                uint32_t bf0, bf1, bf2r, bf3;
                uint32_t ad = brow_base + (uint32_t)(p3 * 2048) + binner;
                LDSM4(bf0, bf1, bf2r, bf3, sB32 + ad);
                MMA16816(c1[p3*2],     ax,  bf0,  bf1);
                MMA16816(c2[p3*2],     as2, bf0,  bf1);
                MMA16816(c1[p3*2 + 1], ax,  bf2r, bf3);
                MMA16816(c2[p3*2 + 1], as2, bf2r, bf3);
            }
            {   // n-tile 6 (x2)
                uint32_t bf0, bf1;
                LDSM2(bf0, bf1, sB32 + brow6 + binner);
                MMA16816(c1[6], ax,  bf0, bf1);
                MMA16816(c2[6], as2, bf0, bf1);
            }
        }
    }

    // ---- row-stat reduction (16 lanes per row -> shfl, atomic accumulate) ----
    #pragma unroll
    for (int j = 0; j < 8; j++) {
        if (j == 7 && wid != 0) continue;   // slot group 7: warp 0 only (uniform)
        float v1 = aSP[j], v2 = aSG[j];
        #pragma unroll
        for (int o = 8; o > 0; o >>= 1) {
            v1 += __shfl_xor_sync(0xffffffffu, v1, o);
            v2 += __shfl_xor_sync(0xffffffffu, v2, o);
        }
        int sl = tid + NT * j;
        if ((lid & 15) == 0) {
            atomicAdd(&g_Sneg[b * Q_ + (sl >> 4)], v1);
            atomicAdd(&g_Ssig[b * Q_ + (sl >> 4)], v2);
        }
    }
    #pragma unroll
    for (int j = 0; j < 4; j++) {
        if (j == 3 && wid >= 4) continue;   // slot group 3: warps 0-3 only
        float v = aM[j];
        #pragma unroll
        for (int o = 8; o > 0; o >>= 1)
            v += __shfl_xor_sync(0xffffffffu, v, o);
        int sl = tid + NT * j;
        if ((lid & 15) == 0)
            atomicAdd(&g_Sm[b * T_ + (sl >> 4)], v);
    }

    // ---- C epilogue: atomic cross-chunk reduction (skip pad rows/cols) ----
    {
        const int r0 = mbase + (lid >> 2);
        const int cb = (lid & 3) * 2;
        float* d1a = g_D1 + (size_t)(b * Q_ + r0) * TP;
        float* d2a = g_D2 + (size_t)(b * Q_ + r0) * TP;
        #pragma unroll
        for (int j = 0; j < 7; j++) {
            int col = j * 8 + cb;
            if (col >= T_) continue;
            if (r0 < Q_) {
                atomicAdd(d1a + col,     c1[j][0]);
                atomicAdd(d1a + col + 1, c1[j][1]);
                atomicAdd(d2a + col,     c2[j][0]);
                atomicAdd(d2a + col + 1, c2[j][1]);
            }
            if (r0 + 8 < Q_) {
                atomicAdd(d1a + 8*TP + col,     c1[j][2]);
                atomicAdd(d1a + 8*TP + col + 1, c1[j][3]);
                atomicAdd(d2a + 8*TP + col,     c2[j][2]);
                atomicAdd(d2a + 8*TP + col + 1, c2[j][3]);
            }
        }
    }
}

// ---------------- kernel 2: class cost + assemble (t-pairs) ----------------
#define TPAIRS (T_/2)
__global__ void combine_kernel(const float* __restrict__ clsq,
                               const int* __restrict__ labw,
                               float* __restrict__ out)
{
    int idx = blockIdx.x * blockDim.x + threadIdx.x;
    if (idx >= B_*Q_*TPAIRS) return;
    int p = idx % TPAIRS;
    int q = (idx / TPAIRS) % Q_;
    int b = idx / (TPAIRS*Q_);
    int t0 = 2 * p;

    float2 D1 = *reinterpret_cast<const float2*>(g_D1 + (size_t)(b * Q_ + q) * TP + t0);
    float2 D2 = *reinterpret_cast<const float2*>(g_D2 + (size_t)(b * Q_ + q) * TP + t0);

    bool is64 = true;
    #pragma unroll
    for (int j = 0; j < 8; j++) is64 &= (labw[2*j + 1] == 0);
    int li0 = b * T_ + t0;
    int l0 = is64 ? labw[2 * li0]       : labw[li0];
    int l1 = is64 ? labw[2 * (li0 + 1)] : labw[li0 + 1];

    const float* cl = clsq + (size_t)(b * Q_ + q) * L_;
    float mx = cl[0];
    #pragma unroll
    for (int k = 1; k < L_; k++) mx = fmaxf(mx, cl[k]);
    float ssum = 0.f;
    #pragma unroll
    for (int k = 0; k < L_; k++) ssum += __expf(cl[k] - mx);
    float inv = __fdividef(1.f, ssum);
    float prob0 = __expf(cl[l0] - mx) * inv;
    float prob1 = __expf(cl[l1] - mx) * inv;

    float Sneg = g_Sneg[b * Q_ + q];
    float Ssig = g_Ssig[b * Q_ + q];
    float Sm0  = g_Sm[li0];
    float Sm1  = g_Sm[li0 + 1];

    const float invG = 1.0f / (float)G_;
    float o0 = (Sneg - D1.x) * invG - prob0
             + 1.0f - (2.0f * D2.x + 1.0f) * __fdividef(1.f, Ssig + Sm0 + 1.0f);
    float o1 = (Sneg - D1.y) * invG - prob1
             + 1.0f - (2.0f * D2.y + 1.0f) * __fdividef(1.f, Ssig + Sm1 + 1.0f);
    *reinterpret_cast<float2*>(out + (size_t)(b * Q_ + q) * T_ + t0) =
        make_float2(o0, o1);
}

// ---------------- launch ----------------
extern "C" void kernel_launch(void* const* d_in, const int* in_sizes, int n_in,
                              void* d_out, int out_size)
{
    const float* x   = (const float*)d_in[0];   // [16,100,16384] f32
    const float* cq  = (const float*)d_in[1];   // [16,100,21]    f32
    const float* m   = (const float*)d_in[2];   // [16,50,16384]  f32
    const int*   lab = (const int*)d_in[3];     // [16,50] labels

    cudaFuncSetAttribute(pm_mma_kernel,
                         cudaFuncAttributeMaxDynamicSharedMemorySize, DYNB);

    zero_kernel<<<(B_*Q_*TP/4 + 255) / 256, 256>>>();

    dim3 grid(NCH, B_);
    pm_mma_kernel<<<grid, NT, DYNB>>>(x, m);

    combine_kernel<<<(B_*Q_*TPAIRS + 255) / 256, 256>>>(cq, lab, (float*)d_out);
}

// round 11
// speedup vs baseline: 1.1642x; 1.1642x over previous
#include <cuda_runtime.h>
#include <cuda_bf16.h>
#include <stdint.h>

#define B_ 16
#define Q_ 100
#define G_ 16384
#define T_ 50
#define L_ 21
#define NCH 18
#define KB 32          // k elements per stage
#define MP 112         // padded M per GEMM (7 warps x 16)
#define NP 56          // padded N
#define TP 56          // g_D row stride
#define NT 224         // threads (7 warps; each warp: x-tile AND sigma-tile)
#define DEPTH 3        // cp.async pipeline depth
#define XSTG (Q_*KB*4) // 12800 B per f32 x stage
#define MSTG (T_*KB*4) //  6400 B per f32 m stage
#define DYNB (DEPTH*(XSTG+MSTG))   // 57600 B dynamic smem

// ---------------- device scratch (module statics, allocation-free) ----------------
__device__ float g_D1[B_*Q_*TP];   // dot(x, m)       (atomic-reduced)
__device__ float g_D2[B_*Q_*TP];   // dot(sig(x), m)  (atomic-reduced)
__device__ float g_Sneg[B_*Q_];
__device__ float g_Ssig[B_*Q_];
__device__ float g_Sm[B_*T_];

// ---------------- helpers ----------------
__device__ __forceinline__ uint32_t smem_u32(const void* p) {
    uint32_t a;
    asm("{ .reg .u64 t; cvta.to.shared.u64 t, %1; cvt.u32.u64 %0, t; }"
        : "=r"(a) : "l"(p));
    return a;
}
__device__ __forceinline__ uint32_t bf2(float lo, float hi) {
    uint32_t r;
    asm("cvt.rn.bf16x2.f32 %0, %1, %2;" : "=r"(r) : "f"(hi), "f"(lo));
    return r;
}
__device__ __forceinline__ float fast_tanh(float x) {
    float r;
    asm("tanh.approx.f32 %0, %1;" : "=f"(r) : "f"(x));
    return r;
}
__device__ __forceinline__ float fast_lg2(float x) {
    float r;
    asm("lg2.approx.f32 %0, %1;" : "=f"(r) : "f"(x));
    return r;
}
__device__ __forceinline__ void cp_async16(uint32_t saddr, const void* gptr) {
    asm volatile("cp.async.cg.shared.global [%0], [%1], 16;"
                 :: "r"(saddr), "l"(gptr) : "memory");
}
#define CP_COMMIT() asm volatile("cp.async.commit_group;" ::: "memory")
#define CP_WAIT2()  asm volatile("cp.async.wait_group 2;"  ::: "memory")
#define LDSM4(r0,r1,r2,r3,addr) \
    asm volatile("ldmatrix.sync.aligned.m8n8.x4.shared.b16 {%0,%1,%2,%3}, [%4];" \
        : "=r"(r0),"=r"(r1),"=r"(r2),"=r"(r3) : "r"(addr))
#define LDSM2(r0,r1,addr) \
    asm volatile("ldmatrix.sync.aligned.m8n8.x2.shared.b16 {%0,%1}, [%2];" \
        : "=r"(r0),"=r"(r1) : "r"(addr))
#define MMA16816(d,a,b0,b1) \
    asm volatile("mma.sync.aligned.m16n8k16.row.col.f32.bf16.bf16.f32 " \
        "{%0,%1,%2,%3},{%4,%5,%6,%7},{%8,%9},{%0,%1,%2,%3};" \
        : "+f"((d)[0]),"+f"((d)[1]),"+f"((d)[2]),"+f"((d)[3]) \
        : "r"((a)[0]),"r"((a)[1]),"r"((a)[2]),"r"((a)[3]),"r"(b0),"r"(b1))

// ---------------- kernel 0: zero accumulators (vectorized) ----------------
__global__ void zero_kernel() {
    int i = blockIdx.x * blockDim.x + threadIdx.x;
    if (i < B_*Q_*TP/4) {
        reinterpret_cast<uint4*>(g_D1)[i] = make_uint4(0,0,0,0);
        reinterpret_cast<uint4*>(g_D2)[i] = make_uint4(0,0,0,0);
    }
    if (i < B_*Q_) { g_Sneg[i] = 0.f; g_Ssig[i] = 0.f; }
    if (i < B_*T_) { g_Sm[i] = 0.f; }
}

// ---------------- kernel 1: cp.async-staged convert + dual HMMA GEMM ----------------
// grid = (NCH, B_), block = 224, 2 CTAs/SM.
// Pipeline: one barrier per stage; MMA runs one stage behind convert so the
// parity-buffered bf16 tiles (s&1 halves of 128B rows) never conflict.
__global__ void __launch_bounds__(NT, 2)
pm_mma_kernel(const float* __restrict__ xg, const float* __restrict__ mg)
{
    __shared__ __align__(1024) __nv_bfloat16 sA[MP*64];   // x     14336 B
    __shared__ __align__(1024) __nv_bfloat16 sS[MP*64];   // sigma 14336 B
    __shared__ __align__(1024) __nv_bfloat16 sB[NP*64];   // m      7168 B
    extern __shared__ __align__(16) char dynsm[];
    char* xstage = dynsm;                 // DEPTH x 12800 B
    char* mstage = dynsm + DEPTH*XSTG;    // DEPTH x  6400 B

    const int b   = blockIdx.y;
    const int c   = blockIdx.x;
    const int tid = threadIdx.x;
    const int wid = tid >> 5;
    const int lid = tid & 31;

    // K split: 512 KB-units over 18 chunks -> 8x29 + 10x28
    const int nu = 28 + (c < 8 ? 1 : 0);
    const int u0 = c * 28 + (c < 8 ? c : 8);

    for (int i = tid; i < MP*64/8; i += NT) {
        reinterpret_cast<uint4*>(sA)[i] = make_uint4(0,0,0,0);
        reinterpret_cast<uint4*>(sS)[i] = make_uint4(0,0,0,0);
    }
    for (int i = tid; i < NP*64/8; i += NT)
        reinterpret_cast<uint4*>(sB)[i] = make_uint4(0,0,0,0);
    __syncthreads();

    const uint32_t sA32  = smem_u32(sA);
    const uint32_t sS32  = smem_u32(sS);
    const uint32_t sB32  = smem_u32(sB);
    const uint32_t xst32 = smem_u32(xstage);
    const uint32_t mst32 = smem_u32(mstage);

    // ---- ldmatrix address precompute (proven formulas) ----
    const int mbase = wid * 16;
    const int arow  = mbase + (lid & 15);
    const uint32_t axor = (uint32_t)((arow & 7) << 4);
    const uint32_t akb0 = (uint32_t)((lid >> 4) << 4);
    const uint32_t aoffk0 = (uint32_t)(arow * 128) + ((0u  + akb0) ^ axor);
    const uint32_t aoffk1 = (uint32_t)(arow * 128) + ((32u + akb0) ^ axor);
    const int bg = lid >> 3, br = lid & 7;
    const uint32_t bxor = (uint32_t)(br << 4);
    const uint32_t bkb0 = (uint32_t)((bg & 1) << 4);
    const uint32_t brow_base = (uint32_t)(((bg >> 1) * 8 + br) * 128);
    const uint32_t brow6     = (uint32_t)((48 + br) * 128);

    // ---- loader slots: x 800 float4 (4/thread), m 400 (2/thread) ----
    bool xact[4];
    const float* xq[4];
    uint32_t sxoff[4];
    #pragma unroll
    for (int j = 0; j < 4; j++) {
        int sl = tid + NT * j;
        xact[j] = sl < Q_ * (KB/4);
        int row = sl >> 3, c4 = sl & 7;
        xq[j] = xg + (size_t)b * Q_ * G_ + (size_t)row * G_ + u0 * KB + c4 * 4;
        sxoff[j] = (uint32_t)(row * 128) + (uint32_t)((c4 * 8) ^ ((row & 7) << 4));
    }
    bool mact[2];
    const float* mq[2];
    uint32_t smoff[2];
    #pragma unroll
    for (int j = 0; j < 2; j++) {
        int sl = tid + NT * j;
        mact[j] = sl < T_ * (KB/4);
        int row = sl >> 3, c4 = sl & 7;
        mq[j] = mg + (size_t)b * T_ * G_ + (size_t)row * G_ + u0 * KB + c4 * 4;
        smoff[j] = (uint32_t)(row * 128) + (uint32_t)((c4 * 8) ^ ((row & 7) << 4));
    }

    float c1[7][4], c2[7][4];
    #pragma unroll
    for (int j = 0; j < 7; j++)
        #pragma unroll
        for (int u = 0; u < 4; u++) { c1[j][u] = 0.f; c2[j][u] = 0.f; }
    float aSP[4], aSG[4], aM[2];
    #pragma unroll
    for (int j = 0; j < 4; j++) { aSP[j] = 0.f; aSG[j] = 0.f; }
    aM[0] = aM[1] = 0.f;

    // MMA phase for tiles of parity pm (0 or 64), as a reusable lambda.
    auto do_mma = [&](uint32_t pm) {
        #pragma unroll
        for (int ks = 0; ks < 2; ks++) {
            const uint32_t aad = ((ks ? aoffk1 : aoffk0) ^ pm);
            uint32_t ax[4], as2[4];
            LDSM4(ax[0],  ax[1],  ax[2],  ax[3],  sA32 + aad);
            LDSM4(as2[0], as2[1], as2[2], as2[3], sS32 + aad);

            const uint32_t binner = (((uint32_t)(ks * 32) + bkb0) ^ bxor) ^ pm;
            #pragma unroll
            for (int p3 = 0; p3 < 3; p3++) {
                uint32_t bf0, bf1, bf2r, bf3;
                uint32_t ad = brow_base + (uint32_t)(p3 * 2048) + binner;
                LDSM4(bf0, bf1, bf2r, bf3, sB32 + ad);
                MMA16816(c1[p3*2],     ax,  bf0,  bf1);
                MMA16816(c2[p3*2],     as2, bf0,  bf1);
                MMA16816(c1[p3*2 + 1], ax,  bf2r, bf3);
                MMA16816(c2[p3*2 + 1], as2, bf2r, bf3);
            }
            {   // n-tile 6 (x2)
                uint32_t bf0, bf1;
                LDSM2(bf0, bf1, sB32 + brow6 + binner);
                MMA16816(c1[6], ax,  bf0, bf1);
                MMA16816(c2[6], as2, bf0, bf1);
            }
        }
    };

    // ---- prologue: issue cp.async for stages 0 and 1 ----
    #pragma unroll
    for (int pre = 0; pre < 2; pre++) {
        if (pre < nu) {
            uint32_t xb = xst32 + pre * XSTG;
            uint32_t mb2 = mst32 + pre * MSTG;
            #pragma unroll
            for (int j = 0; j < 4; j++)
                if (xact[j]) { cp_async16(xb + (uint32_t)((tid + NT*j) * 16), xq[j]); xq[j] += KB; }
            #pragma unroll
            for (int j = 0; j < 2; j++)
                if (mact[j]) { cp_async16(mb2 + (uint32_t)((tid + NT*j) * 16), mq[j]); mq[j] += KB; }
        }
        CP_COMMIT();
    }

    for (int s = 0; s < nu; s++) {
        const uint32_t p64 = (uint32_t)((s & 1) << 6);
        const int buf = s % DEPTH;

        // ---- issue cp.async for stage s+2 (buffer was consumed at s-1) ----
        if (s + 2 < nu) {
            const int nb = (s + 2) % DEPTH;
            uint32_t xb = xst32 + nb * XSTG;
            uint32_t mb2 = mst32 + nb * MSTG;
            #pragma unroll
            for (int j = 0; j < 4; j++)
                if (xact[j]) { cp_async16(xb + (uint32_t)((tid + NT*j) * 16), xq[j]); xq[j] += KB; }
            #pragma unroll
            for (int j = 0; j < 2; j++)
                if (mact[j]) { cp_async16(mb2 + (uint32_t)((tid + NT*j) * 16), mq[j]); mq[j] += KB; }
        }
        CP_COMMIT();

        CP_WAIT2();          // f32 stage s landed
        __syncthreads();     // fills visible; convert(s-1)+MMA(s-2) complete everywhere

        // ---- convert f32 stage s -> bf16 tiles, parity s&1 ----
        const float* xsrc = reinterpret_cast<const float*>(xstage + buf * XSTG);
        const float* msrc = reinterpret_cast<const float*>(mstage + buf * MSTG);
        #pragma unroll
        for (int j = 0; j < 4; j++) {
            if (!xact[j]) continue;
            float4 v = reinterpret_cast<const float4*>(xsrc)[tid + NT * j];
            float f[4] = { v.x, v.y, v.z, v.w };
            float sg[4];
            #pragma unroll
            for (int u = 0; u < 4; u++) {
                float x    = f[u];
                float t    = fast_tanh(0.5f * x);
                float sig  = fmaf(0.5f, t, 0.5f);
                float siga = fmaf(0.5f, fabsf(t), 0.5f);
                sg[u] = sig;
                aSG[j] += sig;
                aSP[j] += fmaxf(x, 0.f) - 0.69314718056f * fast_lg2(siga);
            }
            uint32_t off = sxoff[j] ^ p64;
            *reinterpret_cast<uint2*>(reinterpret_cast<char*>(sA) + off) =
                make_uint2(bf2(f[0], f[1]), bf2(f[2], f[3]));
            *reinterpret_cast<uint2*>(reinterpret_cast<char*>(sS) + off) =
                make_uint2(bf2(sg[0], sg[1]), bf2(sg[2], sg[3]));
        }
        #pragma unroll
        for (int j = 0; j < 2; j++) {
            if (!mact[j]) continue;
            float4 v = reinterpret_cast<const float4*>(msrc)[tid + NT * j];
            aM[j] += v.x + v.y + v.z + v.w;
            uint32_t off = smoff[j] ^ p64;
            *reinterpret_cast<uint2*>(reinterpret_cast<char*>(sB) + off) =
                make_uint2(bf2(v.x, v.y), bf2(v.z, v.w));
        }

        // ---- MMA one stage behind: reads parity (s-1)&1 != s&1, no barrier ----
        if (s > 0) do_mma(p64 ^ 64u);
    }

    // ---- drain: last stage's tiles need one barrier, then final MMA ----
    __syncthreads();
    do_mma((uint32_t)(((nu - 1) & 1) << 6));

    // ---- row-stat reduction (8 lanes per row -> shfl, atomic accumulate) ----
    #pragma unroll
    for (int j = 0; j < 4; j++) {
        float v1 = aSP[j], v2 = aSG[j];
        #pragma unroll
        for (int o = 4; o > 0; o >>= 1) {
            v1 += __shfl_xor_sync(0xffffffffu, v1, o);
            v2 += __shfl_xor_sync(0xffffffffu, v2, o);
        }
        int sl = tid + NT * j;
        if (xact[j] && (lid & 7) == 0) {
            atomicAdd(&g_Sneg[b * Q_ + (sl >> 3)], v1);
            atomicAdd(&g_Ssig[b * Q_ + (sl >> 3)], v2);
        }
    }
    #pragma unroll
    for (int j = 0; j < 2; j++) {
        float v = aM[j];
        #pragma unroll
        for (int o = 4; o > 0; o >>= 1)
            v += __shfl_xor_sync(0xffffffffu, v, o);
        int sl = tid + NT * j;
        if (mact[j] && (lid & 7) == 0)
            atomicAdd(&g_Sm[b * T_ + (sl >> 3)], v);
    }

    // ---- C epilogue: atomic cross-chunk reduction (skip pad rows/cols) ----
    {
        const int r0 = mbase + (lid >> 2);
        const int cb = (lid & 3) * 2;
        float* d1a = g_D1 + (size_t)(b * Q_ + r0) * TP;
        float* d2a = g_D2 + (size_t)(b * Q_ + r0) * TP;
        #pragma unroll
        for (int j = 0; j < 7; j++) {
            int col = j * 8 + cb;
            if (col >= T_) continue;
            if (r0 < Q_) {
                atomicAdd(d1a + col,     c1[j][0]);
                atomicAdd(d1a + col + 1, c1[j][1]);
                atomicAdd(d2a + col,     c2[j][0]);
                atomicAdd(d2a + col + 1, c2[j][1]);
            }
            if (r0 + 8 < Q_) {
                atomicAdd(d1a + 8*TP + col,     c1[j][2]);
                atomicAdd(d1a + 8*TP + col + 1, c1[j][3]);
                atomicAdd(d2a + 8*TP + col,     c2[j][2]);
                atomicAdd(d2a + 8*TP + col + 1, c2[j][3]);
            }
        }
    }
}

// ---------------- kernel 2: class cost + assemble (t-pairs) ----------------
#define TPAIRS (T_/2)
__global__ void combine_kernel(const float* __restrict__ clsq,
                               const int* __restrict__ labw,
                               float* __restrict__ out)
{
    int idx = blockIdx.x * blockDim.x + threadIdx.x;
    if (idx >= B_*Q_*TPAIRS) return;
    int p = idx % TPAIRS;
    int q = (idx / TPAIRS) % Q_;
    int b = idx / (TPAIRS*Q_);
    int t0 = 2 * p;

    float2 D1 = *reinterpret_cast<const float2*>(g_D1 + (size_t)(b * Q_ + q) * TP + t0);
    float2 D2 = *reinterpret_cast<const float2*>(g_D2 + (size_t)(b * Q_ + q) * TP + t0);

    bool is64 = true;
    #pragma unroll
    for (int j = 0; j < 8; j++) is64 &= (labw[2*j + 1] == 0);
    int li0 = b * T_ + t0;
    int l0 = is64 ? labw[2 * li0]       : labw[li0];
    int l1 = is64 ? labw[2 * (li0 + 1)] : labw[li0 + 1];

    const float* cl = clsq + (size_t)(b * Q_ + q) * L_;
    float mx = cl[0];
    #pragma unroll
    for (int k = 1; k < L_; k++) mx = fmaxf(mx, cl[k]);
    float ssum = 0.f;
    #pragma unroll
    for (int k = 0; k < L_; k++) ssum += __expf(cl[k] - mx);
    float inv = __fdividef(1.f, ssum);
    float prob0 = __expf(cl[l0] - mx) * inv;
    float prob1 = __expf(cl[l1] - mx) * inv;

    float Sneg = g_Sneg[b * Q_ + q];
    float Ssig = g_Ssig[b * Q_ + q];
    float Sm0  = g_Sm[li0];
    float Sm1  = g_Sm[li0 + 1];

    const float invG = 1.0f / (float)G_;
    float o0 = (Sneg - D1.x) * invG - prob0
             + 1.0f - (2.0f * D2.x + 1.0f) * __fdividef(1.f, Ssig + Sm0 + 1.0f);
    float o1 = (Sneg - D1.y) * invG - prob1
             + 1.0f - (2.0f * D2.y + 1.0f) * __fdividef(1.f, Ssig + Sm1 + 1.0f);
    *reinterpret_cast<float2*>(out + (size_t)(b * Q_ + q) * T_ + t0) =
        make_float2(o0, o1);
}

// ---------------- launch ----------------
extern "C" void kernel_launch(void* const* d_in, const int* in_sizes, int n_in,
                              void* d_out, int out_size)
{
    const float* x   = (const float*)d_in[0];   // [16,100,16384] f32
    const float* cq  = (const float*)d_in[1];   // [16,100,21]    f32
    const float* m   = (const float*)d_in[2];   // [16,50,16384]  f32
    const int*   lab = (const int*)d_in[3];     // [16,50] labels

    cudaFuncSetAttribute(pm_mma_kernel,
                         cudaFuncAttributeMaxDynamicSharedMemorySize, DYNB);

    zero_kernel<<<(B_*Q_*TP/4 + 255) / 256, 256>>>();

    dim3 grid(NCH, B_);
    pm_mma_kernel<<<grid, NT, DYNB>>>(x, m);

    combine_kernel<<<(B_*Q_*TPAIRS + 255) / 256, 256>>>(cq, lab, (float*)d_out);
}